// round 7
// baseline (speedup 1.0000x reference)
#include <cuda_runtime.h>

// ---------------------------------------------------------------------------
// TinyFormerEncoder R6: 9 warps/SM at FULL register allocation.
// One 288-thread block (9 warps, 36 batches), reg cap 65536/288 = 227 so the
// natural ~206-reg code shape survives (caps <=204 provably trigger a
// spill-heavy 168-reg restructure: R3/R4/R5). Same inner structure as R2:
// 2 rows/thread, dual-row dots, swizzled k/v smem, packed fp32x2 FMA.
// Horizontal reductions now use add.f32x2 (1 packed add + 1 FADD instead of
// 3 FADD) to shave ~5% off the fma-pipe op count.
// ---------------------------------------------------------------------------

namespace {
constexpr int D   = 32;
constexpr int S   = 16;
constexpr int FFN = 64;
constexpr int BATCHES_PER_BLOCK = 36;  // 9 warps * 4 batches
constexpr int THREADS = 288;

// shared memory layout (float offsets)
constexpr int WQT = 0;        // WqT[32][32]  (row j holds Wq[:,j])
constexpr int WKT = 1024;
constexpr int WVT = 2048;
constexpr int WOT = 3072;
constexpr int W1T = 4096;     // W1T[64][32]
constexpr int W2S = 6144;     // W2 as-is [64][32]
constexpr int BQo = 8192;
constexpr int BKo = 8224;
constexpr int BVo = 8256;
constexpr int BOo = 8288;
constexpr int B1o = 8320;     // 64
constexpr int B2o = 8384;     // 32
constexpr int KBo = 8416;     // 36 batches * 16 rows * 32 floats = 18432
constexpr int VBo = KBo + 18432;
constexpr int SMEM_FLOATS = VBo + 18432;   // 45280 floats = 181120 bytes
}

union F2U { float2 f; unsigned long long u; };

__device__ __forceinline__ void ffma2(F2U &acc, F2U a, F2U b) {
    asm("fma.rn.f32x2 %0, %1, %2, %0;" : "+l"(acc.u) : "l"(a.u), "l"(b.u));
}
__device__ __forceinline__ void fadd2(F2U &r, F2U a, F2U b) {
    asm("add.rn.f32x2 %0, %1, %2;" : "=l"(r.u) : "l"(a.u), "l"(b.u));
}

// Dual-row 32-length dot: one weight-row load feeds both rows' accumulators.
__device__ __forceinline__ void dot32x2(const F2U *a, const F2U *b,
                                        const float4 *row4,
                                        float &ra, float &rb) {
    F2U a0, a1, b0, b1;
    a0.f = make_float2(0.f, 0.f); a1.f = make_float2(0.f, 0.f);
    b0.f = make_float2(0.f, 0.f); b1.f = make_float2(0.f, 0.f);
#pragma unroll
    for (int c = 0; c < 8; c++) {
        float4 w = row4[c];
        F2U p, q;
        p.f = make_float2(w.x, w.y);
        q.f = make_float2(w.z, w.w);
        ffma2(a0, a[2*c],   p);
        ffma2(a1, a[2*c+1], q);
        ffma2(b0, b[2*c],   p);
        ffma2(b1, b[2*c+1], q);
    }
    F2U sa, sb;
    fadd2(sa, a0, a1);
    fadd2(sb, b0, b1);
    ra = sa.f.x + sa.f.y;
    rb = sb.f.x + sb.f.y;
}

__device__ __forceinline__ float getx(const F2U *a, int j) {
    return (j & 1) ? a[j >> 1].f.y : a[j >> 1].f.x;
}
__device__ __forceinline__ void setx(F2U *a, int j, float v) {
    if (j & 1) a[j >> 1].f.y = v; else a[j >> 1].f.x = v;
}

__global__ void __launch_bounds__(THREADS, 1)
tinyformer_kernel(const float *__restrict__ x,
                  const float *__restrict__ Wq, const float *__restrict__ bq,
                  const float *__restrict__ Wk, const float *__restrict__ bk,
                  const float *__restrict__ Wv, const float *__restrict__ bv,
                  const float *__restrict__ Wo, const float *__restrict__ bo,
                  const float *__restrict__ W1, const float *__restrict__ b1,
                  const float *__restrict__ W2, const float *__restrict__ b2,
                  float *__restrict__ out, int B)
{
    extern __shared__ float sm[];
    const int tid = threadIdx.x;

    // ---- stage weights (transposed) + biases into smem ----
    for (int i = tid; i < 1024; i += THREADS) {
        int d = i >> 5, j = i & 31;
        sm[WQT + j*32 + d] = Wq[i];
        sm[WKT + j*32 + d] = Wk[i];
        sm[WVT + j*32 + d] = Wv[i];
        sm[WOT + j*32 + d] = Wo[i];
    }
    for (int i = tid; i < 2048; i += THREADS) {
        int d = i >> 6, j = i & 63;
        sm[W1T + j*32 + d] = W1[i];
        sm[W2S + i] = W2[i];
    }
    if (tid < 32) {
        sm[BQo+tid] = bq[tid]; sm[BKo+tid] = bk[tid]; sm[BVo+tid] = bv[tid];
        sm[BOo+tid] = bo[tid]; sm[B2o+tid] = b2[tid];
    }
    if (tid < 64) sm[B1o+tid] = b1[tid];
    __syncthreads();

    const int warp = tid >> 5;
    const int lane = tid & 31;
    const int bw   = lane >> 3;        // batch within warp (0..3)
    const int r0   = lane & 7;         // thread owns rows r0 and r0+8
    const int bl   = warp*4 + bw;      // batch within block (0..35)
    size_t batch = (size_t)blockIdx.x * BATCHES_PER_BLOCK + bl;
    const bool valid = batch < (size_t)B;
    if (!valid) batch = (size_t)B - 1;  // clamp: compute garbage, skip store
    const int bsw  = bw << 1;          // batch-group bank-spread term
    const int ssw  = r0 ^ bsw;         // store swizzle

    // ---- load the two x rows into packed register pairs ----
    const float4 *xpA = reinterpret_cast<const float4*>(x + (batch*S + r0    )*D);
    const float4 *xpB = reinterpret_cast<const float4*>(x + (batch*S + r0 + 8)*D);
    F2U xA[16], xB[16];
#pragma unroll
    for (int c = 0; c < 8; c++) {
        float4 t = xpA[c];
        xA[2*c].f   = make_float2(t.x, t.y);
        xA[2*c+1].f = make_float2(t.z, t.w);
        float4 u = xpB[c];
        xB[2*c].f   = make_float2(u.x, u.y);
        xB[2*c+1].f = make_float2(u.z, u.w);
    }

    float4 *kb4 = reinterpret_cast<float4*>(sm) + (KBo >> 2) + bl * 128;
    float4 *vb4 = reinterpret_cast<float4*>(sm) + (VBo >> 2) + bl * 128;

    // ---- K rows (both) -> swizzled smem ----
#pragma unroll 2
    for (int jc = 0; jc < 8; jc++) {
        float4 bi = reinterpret_cast<const float4*>(sm + BKo)[jc];
        float a0,a1,a2,a3,b0,b1,b2v,b3;
        dot32x2(xA, xB, reinterpret_cast<const float4*>(sm + WKT + (4*jc+0)*32), a0, b0);
        dot32x2(xA, xB, reinterpret_cast<const float4*>(sm + WKT + (4*jc+1)*32), a1, b1);
        dot32x2(xA, xB, reinterpret_cast<const float4*>(sm + WKT + (4*jc+2)*32), a2, b2v);
        dot32x2(xA, xB, reinterpret_cast<const float4*>(sm + WKT + (4*jc+3)*32), a3, b3);
        kb4[r0*8     + (jc ^ ssw)] = make_float4(a0+bi.x, a1+bi.y, a2+bi.z, a3+bi.w);
        kb4[(r0+8)*8 + (jc ^ ssw)] = make_float4(b0+bi.x, b1+bi.y, b2v+bi.z, b3+bi.w);
    }
    // ---- V rows (both) -> swizzled smem ----
#pragma unroll 2
    for (int jc = 0; jc < 8; jc++) {
        float4 bi = reinterpret_cast<const float4*>(sm + BVo)[jc];
        float a0,a1,a2,a3,b0,b1,b2v,b3;
        dot32x2(xA, xB, reinterpret_cast<const float4*>(sm + WVT + (4*jc+0)*32), a0, b0);
        dot32x2(xA, xB, reinterpret_cast<const float4*>(sm + WVT + (4*jc+1)*32), a1, b1);
        dot32x2(xA, xB, reinterpret_cast<const float4*>(sm + WVT + (4*jc+2)*32), a2, b2v);
        dot32x2(xA, xB, reinterpret_cast<const float4*>(sm + WVT + (4*jc+3)*32), a3, b3);
        vb4[r0*8     + (jc ^ ssw)] = make_float4(a0+bi.x, a1+bi.y, a2+bi.z, a3+bi.w);
        vb4[(r0+8)*8 + (jc ^ ssw)] = make_float4(b0+bi.x, b1+bi.y, b2v+bi.z, b3+bi.w);
    }
    // ---- Q rows (both) -> registers, pre-scaled by 1/sqrt(D) ----
    const float SCALE = 0.17677669529663687f;  // 1/sqrt(32)
    F2U qA[16], qB[16];
#pragma unroll 2
    for (int jc = 0; jc < 8; jc++) {
        float4 bi = reinterpret_cast<const float4*>(sm + BQo)[jc];
        float a0,a1,a2,a3,b0,b1,b2v,b3;
        dot32x2(xA, xB, reinterpret_cast<const float4*>(sm + WQT + (4*jc+0)*32), a0, b0);
        dot32x2(xA, xB, reinterpret_cast<const float4*>(sm + WQT + (4*jc+1)*32), a1, b1);
        dot32x2(xA, xB, reinterpret_cast<const float4*>(sm + WQT + (4*jc+2)*32), a2, b2v);
        dot32x2(xA, xB, reinterpret_cast<const float4*>(sm + WQT + (4*jc+3)*32), a3, b3);
        qA[2*jc].f   = make_float2((a0+bi.x)*SCALE, (a1+bi.y)*SCALE);
        qA[2*jc+1].f = make_float2((a2+bi.z)*SCALE, (a3+bi.w)*SCALE);
        qB[2*jc].f   = make_float2((b0+bi.x)*SCALE, (b1+bi.y)*SCALE);
        qB[2*jc+1].f = make_float2((b2v+bi.z)*SCALE, (b3+bi.w)*SCALE);
    }
    __syncwarp();   // k/v visible to the other lanes of this warp

    // ---- scores for both rows: each k row loaded once ----
    float stA[16], stB[16];
#pragma unroll 2
    for (int t = 0; t < 16; t++) {
        const float4 *kr = kb4 + t*8;
        const int tsw = (t & 7) ^ bsw;
        F2U c0,c1,d0,d1;
        c0.f = make_float2(0.f,0.f); c1.f = make_float2(0.f,0.f);
        d0.f = make_float2(0.f,0.f); d1.f = make_float2(0.f,0.f);
#pragma unroll
        for (int c = 0; c < 8; c++) {
            float4 w = kr[c ^ tsw];
            F2U p, q;
            p.f = make_float2(w.x, w.y);
            q.f = make_float2(w.z, w.w);
            ffma2(c0, qA[2*c],   p);
            ffma2(c1, qA[2*c+1], q);
            ffma2(d0, qB[2*c],   p);
            ffma2(d1, qB[2*c+1], q);
        }
        F2U sA2, sB2;
        fadd2(sA2, c0, c1);
        fadd2(sB2, d0, d1);
        stA[t] = sA2.f.x + sA2.f.y;
        stB[t] = sB2.f.x + sB2.f.y;
    }

    // ---- softmax (thread-local, per row) ----
    {
        float mA = stA[0], mB = stB[0];
#pragma unroll
        for (int t = 1; t < 16; t++) { mA = fmaxf(mA, stA[t]); mB = fmaxf(mB, stB[t]); }
        float sA = 0.f, sB = 0.f;
#pragma unroll
        for (int t = 0; t < 16; t++) {
            stA[t] = __expf(stA[t] - mA); sA += stA[t];
            stB[t] = __expf(stB[t] - mB); sB += stB[t];
        }
        float iA = 1.0f / sA, iB = 1.0f / sB;
#pragma unroll
        for (int t = 0; t < 16; t++) { stA[t] *= iA; stB[t] *= iB; }
    }

    // ---- context = attn @ V: each v row loaded once for both rows ----
    F2U cA[16], cB[16];
#pragma unroll
    for (int c = 0; c < 16; c++) { cA[c].f = make_float2(0.f,0.f); cB[c].f = make_float2(0.f,0.f); }
#pragma unroll 2
    for (int t = 0; t < 16; t++) {
        const float4 *vr = vb4 + t*8;
        const int tsw = (t & 7) ^ bsw;
        F2U aA, aB;
        aA.f = make_float2(stA[t], stA[t]);
        aB.f = make_float2(stB[t], stB[t]);
#pragma unroll
        for (int c = 0; c < 8; c++) {
            float4 w = vr[c ^ tsw];
            F2U p, q;
            p.f = make_float2(w.x, w.y);
            q.f = make_float2(w.z, w.w);
            ffma2(cA[2*c],   aA, p);
            ffma2(cA[2*c+1], aA, q);
            ffma2(cB[2*c],   aB, p);
            ffma2(cB[2*c+1], aB, q);
        }
    }

    // ---- y = x + ctx @ Wo + bo  (overwrites xA/xB in place) ----
#pragma unroll 2
    for (int jc = 0; jc < 8; jc++) {
        float4 bi = reinterpret_cast<const float4*>(sm + BOo)[jc];
        float ba[4] = {bi.x, bi.y, bi.z, bi.w};
#pragma unroll
        for (int u = 0; u < 4; u++) {
            int j = 4*jc + u;
            float ya, yb;
            dot32x2(cA, cB, reinterpret_cast<const float4*>(sm + WOT + j*32), ya, yb);
            setx(xA, j, getx(xA, j) + ya + ba[u]);
            setx(xB, j, getx(xB, j) + yb + ba[u]);
        }
    }

    // ---- FFN: z = y + relu(y@W1+b1) @ W2 + b2 ----
    F2U zA[16], zB[16];
#pragma unroll
    for (int c = 0; c < 8; c++) {
        float4 bb = reinterpret_cast<const float4*>(sm + B2o)[c];
        zA[2*c].f   = make_float2(xA[2*c].f.x   + bb.x, xA[2*c].f.y   + bb.y);
        zA[2*c+1].f = make_float2(xA[2*c+1].f.x + bb.z, xA[2*c+1].f.y + bb.w);
        zB[2*c].f   = make_float2(xB[2*c].f.x   + bb.x, xB[2*c].f.y   + bb.y);
        zB[2*c+1].f = make_float2(xB[2*c+1].f.x + bb.z, xB[2*c+1].f.y + bb.w);
    }

#pragma unroll 2
    for (int jc = 0; jc < 8; jc++) {        // 8 chunks of 8 hidden units
        float4 bh0 = reinterpret_cast<const float4*>(sm + B1o)[2*jc];
        float4 bh1 = reinterpret_cast<const float4*>(sm + B1o)[2*jc+1];
        float bh[8] = {bh0.x,bh0.y,bh0.z,bh0.w, bh1.x,bh1.y,bh1.z,bh1.w};
        float hA[8], hB[8];
#pragma unroll
        for (int u = 0; u < 8; u++) {
            int j = jc*8 + u;
            float ha, hb;
            dot32x2(xA, xB, reinterpret_cast<const float4*>(sm + W1T + j*32), ha, hb);
            hA[u] = fmaxf(ha + bh[u], 0.f);
            hB[u] = fmaxf(hb + bh[u], 0.f);
        }
#pragma unroll
        for (int u = 0; u < 8; u++) {
            F2U aA, aB;
            aA.f = make_float2(hA[u], hA[u]);
            aB.f = make_float2(hB[u], hB[u]);
            const float4 *wr = reinterpret_cast<const float4*>(sm + W2S + (jc*8+u)*32);
#pragma unroll
            for (int c = 0; c < 8; c++) {
                float4 w = wr[c];
                F2U p, q;
                p.f = make_float2(w.x, w.y);
                q.f = make_float2(w.z, w.w);
                ffma2(zA[2*c],   aA, p);
                ffma2(zA[2*c+1], aA, q);
                ffma2(zB[2*c],   aB, p);
                ffma2(zB[2*c+1], aB, q);
            }
        }
    }

    // ---- store both z rows (skip if clamped duplicate) ----
    if (valid) {
        float4 *opA = reinterpret_cast<float4*>(out + (batch*S + r0    )*D);
        float4 *opB = reinterpret_cast<float4*>(out + (batch*S + r0 + 8)*D);
#pragma unroll
        for (int c = 0; c < 8; c++) {
            opA[c] = make_float4(zA[2*c].f.x, zA[2*c].f.y, zA[2*c+1].f.x, zA[2*c+1].f.y);
            opB[c] = make_float4(zB[2*c].f.x, zB[2*c].f.y, zB[2*c+1].f.x, zB[2*c+1].f.y);
        }
    }
}

extern "C" void kernel_launch(void* const* d_in, const int* in_sizes, int n_in,
                              void* d_out, int out_size)
{
    const float* x  = (const float*)d_in[0];
    const float* Wq = (const float*)d_in[1];
    const float* bq = (const float*)d_in[2];
    const float* Wk = (const float*)d_in[3];
    const float* bk = (const float*)d_in[4];
    const float* Wv = (const float*)d_in[5];
    const float* bv = (const float*)d_in[6];
    const float* Wo = (const float*)d_in[7];
    const float* bo = (const float*)d_in[8];
    const float* W1 = (const float*)d_in[9];
    const float* b1 = (const float*)d_in[10];
    const float* W2 = (const float*)d_in[11];
    const float* b2 = (const float*)d_in[12];
    float* out = (float*)d_out;

    const int B = in_sizes[0] / (S * D);                                // 65536
    const int blocks = (B + BATCHES_PER_BLOCK - 1) / BATCHES_PER_BLOCK; // 1821
    const size_t smem = SMEM_FLOATS * sizeof(float);                    // 181120 B

    cudaFuncSetAttribute(tinyformer_kernel,
                         cudaFuncAttributeMaxDynamicSharedMemorySize, (int)smem);
    tinyformer_kernel<<<blocks, THREADS, smem>>>(x, Wq, bq, Wk, bk, Wv, bv,
                                                 Wo, bo, W1, b1, W2, b2, out, B);
}

// round 8
// speedup vs baseline: 3.2453x; 3.2453x over previous
#include <cuda_runtime.h>
#include <cuda_bf16.h>
#include <cstdint>

// ---------------------------------------------------------------------------
// TinyFormerEncoder R7: tensor-core rewrite.
// mma.sync.m16n8k16 bf16 with split-precision (hi+lo, 3-term) for ~1e-5 accy.
// One warp = one batch (M=16 rows). Weights pre-transposed + pre-split into
// smem bf16 hi/lo planes (padded rows for conflict-free B-fragment loads).
// K staged row-major (col-major B == row-major K), V staged transposed.
// Softmax via quad shuffles on the C-fragment. All GEMM chaining (P, ctx, y,
// h) is in-register C->A fragment repacking. Residuals kept in exact fp32.
// ---------------------------------------------------------------------------

namespace {
constexpr int THREADS = 128;          // 4 warps
constexpr int NB = 8;                 // batches per warp
constexpr int BATCHES_PER_BLOCK = 4 * NB;  // 32

// ushort (bf16) offsets in dynamic smem
constexpr int WQH = 0,     WQL = 1152;
constexpr int WKH = 2304,  WKL = 3456;
constexpr int WVH = 4608,  WVL = 5760;
constexpr int WOH = 6912,  WOL = 8064;     // 32x32 mats, row stride 36
constexpr int W1H = 9216,  W1L = 11520;    // 64 rows x stride 36
constexpr int W2H = 13824, W2L = 16128;    // 32 rows x stride 72
constexpr int BIASU  = 18432;              // float bias block starts here
constexpr int STAGEU = 18880;              // per-warp staging base (ushort)
constexpr int WARP_STAGE = 2688;
constexpr int KH = 0, KL = 576;            // K planes: 16 rows x stride 36
constexpr int VTH = 1152, VTL = 1920;      // vT planes: 32 rows x stride 24
constexpr int SMEM_BYTES = (STAGEU + 4 * WARP_STAGE) * 2;  // 59264
constexpr float SCALE = 0.17677669529663687f;  // 1/sqrt(32)
}

// pack two f32 into bf16x2: 'lo' element -> low half, 'hi' element -> high half
__device__ __forceinline__ uint32_t packbf(float lo, float hi) {
    uint32_t r;
    asm("cvt.rn.bf16x2.f32 %0, %1, %2;" : "=r"(r) : "f"(hi), "f"(lo));
    return r;
}
__device__ __forceinline__ float lo2f(uint32_t v) { return __uint_as_float(v << 16); }
__device__ __forceinline__ float hi2f(uint32_t v) { return __uint_as_float(v & 0xffff0000u); }

// split pair (e0,e1) into hi-plane and lo-plane bf16x2 regs
__device__ __forceinline__ void split2(float e0, float e1, uint32_t &h, uint32_t &l) {
    h = packbf(e0, e1);
    l = packbf(e0 - lo2f(h), e1 - hi2f(h));
}

__device__ __forceinline__ void mma16816(float &c0, float &c1, float &c2, float &c3,
                                         uint32_t a0, uint32_t a1, uint32_t a2, uint32_t a3,
                                         uint32_t b0, uint32_t b1) {
    asm("mma.sync.aligned.m16n8k16.row.col.f32.bf16.bf16.f32 "
        "{%0,%1,%2,%3}, {%4,%5,%6,%7}, {%8,%9}, {%0,%1,%2,%3};"
        : "+f"(c0), "+f"(c1), "+f"(c2), "+f"(c3)
        : "r"(a0), "r"(a1), "r"(a2), "r"(a3), "r"(b0), "r"(b1));
}

// C-fragment (NCH n-chunks) -> A-fragments (NCH/2 k-chunks), split hi/lo.
template <int KCH>
__device__ __forceinline__ void c2a(const float *C, uint32_t *ah, uint32_t *al) {
#pragma unroll
    for (int kc = 0; kc < KCH; kc++) {
        split2(C[8*kc+0], C[8*kc+1], ah[kc*4+0], al[kc*4+0]);   // (g,   kbase+2t,+1)
        split2(C[8*kc+2], C[8*kc+3], ah[kc*4+1], al[kc*4+1]);   // (g+8, kbase+2t,+1)
        split2(C[8*kc+4], C[8*kc+5], ah[kc*4+2], al[kc*4+2]);   // (g,   kbase+8+2t,+1)
        split2(C[8*kc+6], C[8*kc+7], ah[kc*4+3], al[kc*4+3]);   // (g+8, kbase+8+2t,+1)
    }
}

// 3-term split GEMM: C[NCH*4] += A x W, B-frags from hi/lo planes (row stride RS)
template <int KCH, int NCH, int RS>
__device__ __forceinline__ void gemm(float *C, const uint32_t *ah, const uint32_t *al,
                                     const unsigned short *wh, const unsigned short *wl,
                                     int g, int t) {
#pragma unroll
    for (int j = 0; j < NCH; j++) {
        float *c = C + j*4;
#pragma unroll
        for (int kc = 0; kc < KCH; kc++) {
            const unsigned short *ph = wh + (8*j + g)*RS + kc*16 + 2*t;
            const unsigned short *pl = wl + (8*j + g)*RS + kc*16 + 2*t;
            uint32_t bh0 = *(const uint32_t*)ph,        bh1 = *(const uint32_t*)(ph + 8);
            uint32_t bl0 = *(const uint32_t*)pl,        bl1 = *(const uint32_t*)(pl + 8);
            mma16816(c[0],c[1],c[2],c[3], ah[kc*4],ah[kc*4+1],ah[kc*4+2],ah[kc*4+3], bh0,bh1);
            mma16816(c[0],c[1],c[2],c[3], ah[kc*4],ah[kc*4+1],ah[kc*4+2],ah[kc*4+3], bl0,bl1);
            mma16816(c[0],c[1],c[2],c[3], al[kc*4],al[kc*4+1],al[kc*4+2],al[kc*4+3], bh0,bh1);
        }
    }
}

__global__ void __launch_bounds__(THREADS, 2)
tinyformer_tc_kernel(const float *__restrict__ x,
                     const float *__restrict__ Wq, const float *__restrict__ bq,
                     const float *__restrict__ Wk, const float *__restrict__ bk,
                     const float *__restrict__ Wv, const float *__restrict__ bv,
                     const float *__restrict__ Wo, const float *__restrict__ bo,
                     const float *__restrict__ W1, const float *__restrict__ b1,
                     const float *__restrict__ W2, const float *__restrict__ b2,
                     float *__restrict__ out, int B)
{
    extern __shared__ unsigned short sm16[];
    float *smf = (float*)(sm16 + BIASU);   // bias block (224 floats)
    const int tid = threadIdx.x;

    // ---- stage weights: transpose + split into bf16 hi/lo planes ----
    for (int i = tid; i < 1024; i += THREADS) {
        int d = i >> 5, j = i & 31;           // W[d][j] -> WT[j][d]
        int o = j*36 + d;
        {   float v = Wq[i]; uint32_t p = packbf(v, 0.f);
            sm16[WQH + o] = (unsigned short)p;
            sm16[WQL + o] = (unsigned short)packbf(v - lo2f(p), 0.f); }
        {   float v = Wk[i]; uint32_t p = packbf(v, 0.f);
            sm16[WKH + o] = (unsigned short)p;
            sm16[WKL + o] = (unsigned short)packbf(v - lo2f(p), 0.f); }
        {   float v = Wv[i]; uint32_t p = packbf(v, 0.f);
            sm16[WVH + o] = (unsigned short)p;
            sm16[WVL + o] = (unsigned short)packbf(v - lo2f(p), 0.f); }
        {   float v = Wo[i]; uint32_t p = packbf(v, 0.f);
            sm16[WOH + o] = (unsigned short)p;
            sm16[WOL + o] = (unsigned short)packbf(v - lo2f(p), 0.f); }
    }
    for (int i = tid; i < 2048; i += THREADS) {
        {   int d = i >> 6, j = i & 63;       // W1[d][j] -> W1T[j][d]
            float v = W1[i]; uint32_t p = packbf(v, 0.f);
            sm16[W1H + j*36 + d] = (unsigned short)p;
            sm16[W1L + j*36 + d] = (unsigned short)packbf(v - lo2f(p), 0.f); }
        {   int h = i >> 5, j = i & 31;       // W2[h][j] -> W2T[j][h]
            float v = W2[i]; uint32_t p = packbf(v, 0.f);
            sm16[W2H + j*72 + h] = (unsigned short)p;
            sm16[W2L + j*72 + h] = (unsigned short)packbf(v - lo2f(p), 0.f); }
    }
    if (tid < 32) {
        smf[0   + tid] = bq[tid]; smf[32 + tid] = bk[tid]; smf[64 + tid] = bv[tid];
        smf[96  + tid] = bo[tid]; smf[192 + tid] = b2[tid];
    }
    if (tid < 64) smf[128 + tid] = b1[tid];
    __syncthreads();

    const int warp = tid >> 5, lane = tid & 31;
    const int g = lane >> 2, t = lane & 3;    // mma group / thread-in-group
    unsigned short *stg = sm16 + STAGEU + warp * WARP_STAGE;
    unsigned short *kh  = stg + KH,  *kl  = stg + KL;
    unsigned short *vth = stg + VTH, *vtl = stg + VTL;

    for (int it = 0; it < NB; it++) {
        size_t batch = (size_t)blockIdx.x * BATCHES_PER_BLOCK + warp * NB + it;
        if (batch >= (size_t)B) continue;     // warp-uniform

        // ---- x in C-fragment layout (fp32, exact for residual) ----
        const float2 *xp2 = (const float2*)(x + batch * 512);
        float xc[16];
#pragma unroll
        for (int nc = 0; nc < 4; nc++) {
            float2 p0 = xp2[g*16 + nc*4 + t];
            float2 p1 = xp2[(g+8)*16 + nc*4 + t];
            xc[nc*4+0] = p0.x; xc[nc*4+1] = p0.y;
            xc[nc*4+2] = p1.x; xc[nc*4+3] = p1.y;
        }
        uint32_t xah[8], xal[8];
        c2a<2>(xc, xah, xal);

        float C[16];

        // ---- K = x@Wk + bk -> split-stored row-major ----
#pragma unroll
        for (int i2 = 0; i2 < 16; i2++) C[i2] = 0.f;
        gemm<2,4,36>(C, xah, xal, sm16 + WKH, sm16 + WKL, g, t);
#pragma unroll
        for (int nc = 0; nc < 4; nc++) {
            float2 bb = *(const float2*)(smf + 32 + 8*nc + 2*t);
            uint32_t h0, l0, h1, l1;
            split2(C[nc*4+0] + bb.x, C[nc*4+1] + bb.y, h0, l0);
            split2(C[nc*4+2] + bb.x, C[nc*4+3] + bb.y, h1, l1);
            int c0 = nc*8 + 2*t;
            *(uint32_t*)(kh + g*36     + c0) = h0;
            *(uint32_t*)(kl + g*36     + c0) = l0;
            *(uint32_t*)(kh + (g+8)*36 + c0) = h1;
            *(uint32_t*)(kl + (g+8)*36 + c0) = l1;
        }

        // ---- V = x@Wv + bv -> split-stored TRANSPOSED (vT[d][t]) ----
#pragma unroll
        for (int i2 = 0; i2 < 16; i2++) C[i2] = 0.f;
        gemm<2,4,36>(C, xah, xal, sm16 + WVH, sm16 + WVL, g, t);
#pragma unroll
        for (int nc = 0; nc < 4; nc++) {
            float2 bb = *(const float2*)(smf + 64 + 8*nc + 2*t);
            float e[4] = { C[nc*4+0] + bb.x, C[nc*4+1] + bb.y,
                           C[nc*4+2] + bb.x, C[nc*4+3] + bb.y };
            int col[4] = { 8*nc + 2*t, 8*nc + 2*t + 1, 8*nc + 2*t, 8*nc + 2*t + 1 };
            int row[4] = { g, g, g + 8, g + 8 };
#pragma unroll
            for (int m = 0; m < 4; m++) {
                uint32_t p = packbf(e[m], 0.f);
                vth[col[m]*24 + row[m]] = (unsigned short)p;
                vtl[col[m]*24 + row[m]] = (unsigned short)packbf(e[m] - lo2f(p), 0.f);
            }
        }

        // ---- Q = (x@Wq + bq) * scale -> A-fragments ----
#pragma unroll
        for (int i2 = 0; i2 < 16; i2++) C[i2] = 0.f;
        gemm<2,4,36>(C, xah, xal, sm16 + WQH, sm16 + WQL, g, t);
        float qc[16];
#pragma unroll
        for (int nc = 0; nc < 4; nc++) {
            float2 bb = *(const float2*)(smf + 0 + 8*nc + 2*t);
            qc[nc*4+0] = (C[nc*4+0] + bb.x) * SCALE;
            qc[nc*4+1] = (C[nc*4+1] + bb.y) * SCALE;
            qc[nc*4+2] = (C[nc*4+2] + bb.x) * SCALE;
            qc[nc*4+3] = (C[nc*4+3] + bb.y) * SCALE;
        }
        uint32_t qah[8], qal[8];
        c2a<2>(qc, qah, qal);

        __syncwarp();   // K/V staging visible within warp

        // ---- S = Q @ K^T  (B col-major == K row-major) ----
        float s[8];
#pragma unroll
        for (int i2 = 0; i2 < 8; i2++) s[i2] = 0.f;
        gemm<2,2,36>(s, qah, qal, kh, kl, g, t);

        // ---- softmax (rows g and g+8; quad shuffles across t) ----
        float m0 = fmaxf(fmaxf(s[0], s[1]), fmaxf(s[4], s[5]));
        float m1 = fmaxf(fmaxf(s[2], s[3]), fmaxf(s[6], s[7]));
        m0 = fmaxf(m0, __shfl_xor_sync(0xffffffffu, m0, 1));
        m0 = fmaxf(m0, __shfl_xor_sync(0xffffffffu, m0, 2));
        m1 = fmaxf(m1, __shfl_xor_sync(0xffffffffu, m1, 1));
        m1 = fmaxf(m1, __shfl_xor_sync(0xffffffffu, m1, 2));
        s[0] = __expf(s[0] - m0); s[1] = __expf(s[1] - m0);
        s[4] = __expf(s[4] - m0); s[5] = __expf(s[5] - m0);
        s[2] = __expf(s[2] - m1); s[3] = __expf(s[3] - m1);
        s[6] = __expf(s[6] - m1); s[7] = __expf(s[7] - m1);
        float t0 = s[0] + s[1] + s[4] + s[5];
        float t1 = s[2] + s[3] + s[6] + s[7];
        t0 += __shfl_xor_sync(0xffffffffu, t0, 1);
        t0 += __shfl_xor_sync(0xffffffffu, t0, 2);
        t1 += __shfl_xor_sync(0xffffffffu, t1, 1);
        t1 += __shfl_xor_sync(0xffffffffu, t1, 2);
        float i0 = 1.f / t0, i1 = 1.f / t1;
        s[0] *= i0; s[1] *= i0; s[4] *= i0; s[5] *= i0;
        s[2] *= i1; s[3] *= i1; s[6] *= i1; s[7] *= i1;

        // ---- P -> A (m16k16, one chunk) ----
        uint32_t pah[4], pal[4];
        split2(s[0], s[1], pah[0], pal[0]);
        split2(s[2], s[3], pah[1], pal[1]);
        split2(s[4], s[5], pah[2], pal[2]);
        split2(s[6], s[7], pah[3], pal[3]);

        // ---- ctx = P @ V  (B from vT planes) ----
        float ctx[16];
#pragma unroll
        for (int i2 = 0; i2 < 16; i2++) ctx[i2] = 0.f;
        gemm<1,4,24>(ctx, pah, pal, vth, vtl, g, t);

        // ---- y = x + ctx@Wo + bo ----
        uint32_t cah[8], cal[8];
        c2a<2>(ctx, cah, cal);
        float yv[16];
#pragma unroll
        for (int i2 = 0; i2 < 16; i2++) yv[i2] = 0.f;
        gemm<2,4,36>(yv, cah, cal, sm16 + WOH, sm16 + WOL, g, t);
#pragma unroll
        for (int nc = 0; nc < 4; nc++) {
            float2 bb = *(const float2*)(smf + 96 + 8*nc + 2*t);
            yv[nc*4+0] += xc[nc*4+0] + bb.x;
            yv[nc*4+1] += xc[nc*4+1] + bb.y;
            yv[nc*4+2] += xc[nc*4+2] + bb.x;
            yv[nc*4+3] += xc[nc*4+3] + bb.y;
        }

        // ---- h = relu(y@W1 + b1)  [16x64] ----
        uint32_t yah[8], yal[8];
        c2a<2>(yv, yah, yal);
        float hbuf[32];
#pragma unroll
        for (int i2 = 0; i2 < 32; i2++) hbuf[i2] = 0.f;
        gemm<2,8,36>(hbuf, yah, yal, sm16 + W1H, sm16 + W1L, g, t);
#pragma unroll
        for (int nc = 0; nc < 8; nc++) {
            float2 bb = *(const float2*)(smf + 128 + 8*nc + 2*t);
            hbuf[nc*4+0] = fmaxf(hbuf[nc*4+0] + bb.x, 0.f);
            hbuf[nc*4+1] = fmaxf(hbuf[nc*4+1] + bb.y, 0.f);
            hbuf[nc*4+2] = fmaxf(hbuf[nc*4+2] + bb.x, 0.f);
            hbuf[nc*4+3] = fmaxf(hbuf[nc*4+3] + bb.y, 0.f);
        }

        // ---- z = y + h@W2 + b2 ----
        uint32_t hah[16], hal[16];
        c2a<4>(hbuf, hah, hal);
        float zv[16];
#pragma unroll
        for (int i2 = 0; i2 < 16; i2++) zv[i2] = 0.f;
        gemm<4,4,72>(zv, hah, hal, sm16 + W2H, sm16 + W2L, g, t);

        float2 *op2 = (float2*)(out + batch * 512);
#pragma unroll
        for (int nc = 0; nc < 4; nc++) {
            float2 bb = *(const float2*)(smf + 192 + 8*nc + 2*t);
            op2[g*16 + nc*4 + t]     = make_float2(zv[nc*4+0] + yv[nc*4+0] + bb.x,
                                                   zv[nc*4+1] + yv[nc*4+1] + bb.y);
            op2[(g+8)*16 + nc*4 + t] = make_float2(zv[nc*4+2] + yv[nc*4+2] + bb.x,
                                                   zv[nc*4+3] + yv[nc*4+3] + bb.y);
        }
        __syncwarp();   // before next iteration overwrites K/V staging
    }
}

extern "C" void kernel_launch(void* const* d_in, const int* in_sizes, int n_in,
                              void* d_out, int out_size)
{
    const float* x  = (const float*)d_in[0];
    const float* Wq = (const float*)d_in[1];
    const float* bq = (const float*)d_in[2];
    const float* Wk = (const float*)d_in[3];
    const float* bk = (const float*)d_in[4];
    const float* Wv = (const float*)d_in[5];
    const float* bv = (const float*)d_in[6];
    const float* Wo = (const float*)d_in[7];
    const float* bo = (const float*)d_in[8];
    const float* W1 = (const float*)d_in[9];
    const float* b1 = (const float*)d_in[10];
    const float* W2 = (const float*)d_in[11];
    const float* b2 = (const float*)d_in[12];
    float* out = (float*)d_out;

    const int B = in_sizes[0] / 512;                                    // 65536
    const int blocks = (B + BATCHES_PER_BLOCK - 1) / BATCHES_PER_BLOCK; // 2048

    cudaFuncSetAttribute(tinyformer_tc_kernel,
                         cudaFuncAttributeMaxDynamicSharedMemorySize, SMEM_BYTES);
    tinyformer_tc_kernel<<<blocks, THREADS, SMEM_BYTES>>>(x, Wq, bq, Wk, bk, Wv, bv,
                                                          Wo, bo, W1, b1, W2, b2, out, B);
}